// round 6
// baseline (speedup 1.0000x reference)
#include <cuda_runtime.h>
#include <cuda_bf16.h>
#include <math.h>
#include <stdint.h>

// Problem constants (fixed by the reference)
#define NNODES 10000
#define NEDGES 320000
#define DIN    512
#define DHID   2048
#define NCLS   40

#define GA_ROWS 10112             // 79 * 128 (padded M; pad rows stay zero)

// GEMM1: A'[M x 1024]=[hi|lo], B'(W1^T)[2048 x 1536]=[hi|lo|hi], 24 K-chunks
#define KA1     1024
#define KB1     1536
#define BM      128
#define BN      256
#define BK      64                // 64 bf16 = 128 B per SMEM row
#define NKIT    24

// GEMM2: A2'(h')[M x 4096]=[hi|lo], B2'(W2^T)[48 x 4096]=[hi|lo], 96 K-chunks
#define KA2     4096
#define BM2     64
#define BN2     48                // padded from 40
#define NKIT2   96

// ---------------------------------------------------------------------------
// Device scratch (static globals: no runtime allocation allowed)
// ---------------------------------------------------------------------------
__device__ int   g_cnt[NNODES];
__device__ int   g_rowptr[NNODES + 1];
__device__ int   g_cursor[NNODES];
__device__ float g_dinv[NNODES];
__device__ int   g_csr_src[NEDGES];
__device__ float g_csr_coef[NEDGES];
__device__ __nv_bfloat16 g_Abf[(size_t)GA_ROWS * KA1];   // 20.7 MB
__device__ __nv_bfloat16 g_Bbf[(size_t)DHID * KB1];      // 6.3 MB
__device__ __nv_bfloat16 g_hbf[(size_t)GA_ROWS * KA2];   // 82.8 MB
__device__ __nv_bfloat16 g_W2bf[(size_t)BN2 * KA2];      // 393 KB
__device__ float g_t[(size_t)NNODES * NCLS];             // 1.6 MB

// ---------------------------------------------------------------------------
// PTX helpers (baseline sm_80+ ISA: cp.async / ldmatrix / mma.sync)
// ---------------------------------------------------------------------------
__device__ __forceinline__ uint32_t smem_u32(const void* p) {
    uint32_t a;
    asm("{ .reg .u64 t; cvta.to.shared.u64 t, %1; cvt.u32.u64 %0, t; }"
        : "=r"(a) : "l"(p));
    return a;
}
__device__ __forceinline__ void cp_async16(uint32_t saddr, const void* gaddr) {
    asm volatile("cp.async.cg.shared.global [%0], [%1], 16;"
                 :: "r"(saddr), "l"(gaddr) : "memory");
}
__device__ __forceinline__ void cp_commit() {
    asm volatile("cp.async.commit_group;" ::: "memory");
}
template <int N>
__device__ __forceinline__ void cp_wait() {
    asm volatile("cp.async.wait_group %0;" :: "n"(N) : "memory");
}
__device__ __forceinline__ void ldsm_x4(uint32_t addr, uint32_t& r0, uint32_t& r1,
                                        uint32_t& r2, uint32_t& r3) {
    asm volatile("ldmatrix.sync.aligned.m8n8.x4.shared.b16 {%0,%1,%2,%3}, [%4];"
                 : "=r"(r0), "=r"(r1), "=r"(r2), "=r"(r3) : "r"(addr));
}
__device__ __forceinline__ void mma_bf16(float* d, const uint32_t* a, const uint32_t* b) {
    asm volatile(
        "mma.sync.aligned.m16n8k16.row.col.f32.bf16.bf16.f32 "
        "{%0,%1,%2,%3}, {%4,%5,%6,%7}, {%8,%9}, {%0,%1,%2,%3};"
        : "+f"(d[0]), "+f"(d[1]), "+f"(d[2]), "+f"(d[3])
        : "r"(a[0]), "r"(a[1]), "r"(a[2]), "r"(a[3]), "r"(b[0]), "r"(b[1]));
}

union BfPair { __nv_bfloat16 h[2]; uint32_t u; };

// ---------------------------------------------------------------------------
// CSR construction
// ---------------------------------------------------------------------------
__global__ void zero_cnt_kernel() {
    for (int i = blockIdx.x * blockDim.x + threadIdx.x; i < NNODES;
         i += gridDim.x * blockDim.x)
        g_cnt[i] = 0;
}
__global__ void count_kernel(const int* __restrict__ dst) {
    int e = blockIdx.x * blockDim.x + threadIdx.x;
    if (e < NEDGES) atomicAdd(&g_cnt[dst[e]], 1);
}
__global__ void scan_kernel() {
    __shared__ int sh[1024];
    __shared__ int carry;
    int tid = threadIdx.x;
    if (tid == 0) { carry = 0; g_rowptr[0] = 0; }
    __syncthreads();
    for (int base = 0; base < NNODES; base += 1024) {
        int i = base + tid;
        int v = (i < NNODES) ? g_cnt[i] : 0;
        sh[tid] = v;
        __syncthreads();
        #pragma unroll
        for (int off = 1; off < 1024; off <<= 1) {
            int t = (tid >= off) ? sh[tid - off] : 0;
            __syncthreads();
            sh[tid] += t;
            __syncthreads();
        }
        int incl = sh[tid];
        if (i < NNODES) g_rowptr[i + 1] = carry + incl;
        __syncthreads();
        if (tid == 1023) carry += sh[1023];
        __syncthreads();
    }
}
__global__ void dinv_cursor_kernel() {
    for (int i = blockIdx.x * blockDim.x + threadIdx.x; i < NNODES;
         i += gridDim.x * blockDim.x) {
        g_dinv[i]   = rsqrtf((float)g_cnt[i] + 1.0f);
        g_cursor[i] = g_rowptr[i];
    }
}
__global__ void fill_kernel(const int* __restrict__ src, const int* __restrict__ dst) {
    int e = blockIdx.x * blockDim.x + threadIdx.x;
    if (e >= NEDGES) return;
    int s = src[e], d = dst[e];
    int p = atomicAdd(&g_cursor[d], 1);
    g_csr_src[p]  = s;
    g_csr_coef[p] = g_dinv[s] * g_dinv[d];
}

// ---------------------------------------------------------------------------
// W1 prep (tiled transpose): g_Bbf[n] = [hi(512) | lo(512) | hi(512)]
// ---------------------------------------------------------------------------
__global__ void w1prep_kernel(const float* __restrict__ W1) {
    __shared__ float tile[32][33];
    int k0 = blockIdx.x * 32, n0 = blockIdx.y * 32;
    int tx = threadIdx.x, ty = threadIdx.y;
    #pragma unroll
    for (int j = 0; j < 4; j++)
        tile[ty + 8 * j][tx] = W1[(size_t)(k0 + ty + 8 * j) * DHID + n0 + tx];
    __syncthreads();
    #pragma unroll
    for (int j = 0; j < 4; j++) {
        int n = n0 + ty + 8 * j;
        int k = k0 + tx;
        float w = tile[tx][ty + 8 * j];
        __nv_bfloat16 hi = __float2bfloat16(w);
        __nv_bfloat16 lo = __float2bfloat16(w - __bfloat162float(hi));
        __nv_bfloat16* row = &g_Bbf[(size_t)n * KB1];
        row[k]        = hi;
        row[512 + k]  = lo;
        row[1024 + k] = hi;
    }
}

// ---------------------------------------------------------------------------
// W2 prep: g_W2bf[n] = [hi(2048) | lo(2048)], rows 40..47 zero
// ---------------------------------------------------------------------------
__global__ void w2prep_kernel(const float* __restrict__ W2) {
    int n = blockIdx.x;                 // 0..47
    __nv_bfloat16* row = &g_W2bf[(size_t)n * KA2];
    for (int k = threadIdx.x; k < DHID; k += blockDim.x) {
        float w = (n < NCLS) ? W2[(size_t)k * NCLS + n] : 0.0f;
        __nv_bfloat16 hi = __float2bfloat16(w);
        __nv_bfloat16 lo = __float2bfloat16(w - __bfloat162float(hi));
        row[k]        = hi;
        row[2048 + k] = lo;
    }
}

// ---------------------------------------------------------------------------
// Layer-1 propagate + split pack: A'[i] = [hi | lo]
// ---------------------------------------------------------------------------
__global__ void gather1_kernel(const float* __restrict__ x) {
    int i = blockIdx.x;
    int f4 = threadIdx.x;
    float di = g_dinv[i];
    float self = di * di;
    float4 xv = ((const float4*)&x[(size_t)i * DIN])[f4];
    float4 acc;
    acc.x = self * xv.x; acc.y = self * xv.y;
    acc.z = self * xv.z; acc.w = self * xv.w;
    int beg = g_rowptr[i], end = g_rowptr[i + 1];
    for (int j = beg; j < end; j++) {
        int s = g_csr_src[j];
        float c = g_csr_coef[j];
        float4 v = ((const float4*)&x[(size_t)s * DIN])[f4];
        acc.x += c * v.x; acc.y += c * v.y;
        acc.z += c * v.z; acc.w += c * v.w;
    }
    float a[4] = {acc.x, acc.y, acc.z, acc.w};
    union { __nv_bfloat16 h[4]; uint2 u; } hp, lp;
    #pragma unroll
    for (int t = 0; t < 4; t++) {
        hp.h[t] = __float2bfloat16(a[t]);
        lp.h[t] = __float2bfloat16(a[t] - __bfloat162float(hp.h[t]));
    }
    int k = f4 * 4;
    __nv_bfloat16* row = &g_Abf[(size_t)i * KA1];
    *(uint2*)&row[k]       = hp.u;
    *(uint2*)&row[512 + k] = lp.u;
}

// ---------------------------------------------------------------------------
// GEMM1 (mma.sync bf16): h' = relu(A' @ B'^T + b1) stored split-bf16 [hi|lo]
// 128x256x64 tile, 512 threads (16 warps, 4x4, warp tile 32x64), 3-stage
// cp.async pipeline. Per-chunk order: wait(stage kt) -> barrier ->
// issue load(kt+2) -> compute(stage kt).  One barrier per chunk, race-free.
// ---------------------------------------------------------------------------
#define STAGE_BYTES (BM * BK * 2 + BN * BK * 2)   // 49152
#define GEMM1_SMEM  (3 * STAGE_BYTES)             // 147456

__global__ __launch_bounds__(512, 1)
void gemm1_mma_kernel(const float* __restrict__ bias) {
    extern __shared__ char dsm[];
    const uint32_t sbase = smem_u32(dsm);
    const int tid  = threadIdx.x;
    const int wid  = tid >> 5;
    const int lane = tid & 31;
    const int warp_m = wid & 3;       // 4 warps over M=128
    const int warp_n = wid >> 2;      // 4 warps over N=256 (64 each)
    const int block_n = blockIdx.x * BN;
    const int block_m = blockIdx.y * BM;

    uint32_t sA[3], sB[3];
    #pragma unroll
    for (int s = 0; s < 3; s++) {
        sA[s] = sbase + s * STAGE_BYTES;
        sB[s] = sA[s] + (uint32_t)(BM * BK * 2);
    }

    auto load_stage = [&](int kt, int s) {
        const int ka = ((kt < 8) ? kt : kt - 8) * BK;
        const int kb = kt * BK;
        #pragma unroll
        for (int i = 0; i < 2; i++) {                 // A: 1024 chunks
            int t = tid + i * 512;
            int row = t >> 3, c = t & 7;
            uint32_t sw = (uint32_t)(row << 7) + (uint32_t)(((c ^ (row & 7)) << 4));
            cp_async16(sA[s] + sw, &g_Abf[(size_t)(block_m + row) * KA1 + ka + c * 8]);
        }
        #pragma unroll
        for (int i = 0; i < 4; i++) {                 // B: 2048 chunks
            int t = tid + i * 512;
            int row = t >> 3, c = t & 7;
            uint32_t sw = (uint32_t)(row << 7) + (uint32_t)(((c ^ (row & 7)) << 4));
            cp_async16(sB[s] + sw, &g_Bbf[(size_t)(block_n + row) * KB1 + kb + c * 8]);
        }
        cp_commit();
    };

    const int grp  = lane >> 3;
    const int lrow = lane & 7;
    const int arow0 = warp_m * 32 + ((grp & 1) << 3) + lrow;
    const int arow1 = arow0 + 16;
    const int akc_half = grp >> 1;
    const int brow_base = warp_n * 64 + ((grp >> 1) << 3) + lrow;
    const int bkc_half = grp & 1;

    float acc[2][8][4];
    #pragma unroll
    for (int i = 0; i < 2; i++)
        #pragma unroll
        for (int j = 0; j < 8; j++)
            #pragma unroll
            for (int q = 0; q < 4; q++) acc[i][j][q] = 0.0f;

    load_stage(0, 0);
    load_stage(1, 1);

    for (int kt = 0; kt < NKIT; kt++) {
        const int cur = kt % 3;
        // make stage kt visible: this thread's groups <= kt complete, then
        // barrier publishes every thread's writes.
        if (kt <= NKIT - 2) cp_wait<1>();
        else                cp_wait<0>();
        __syncthreads();
        // prefetch chunk kt+2 into buffer (kt+2)%3 == (kt-1)%3 (freed: all
        // warps finished its compute before this barrier).
        if (kt + 2 < NKIT) load_stage(kt + 2, (kt + 2) % 3);

        #pragma unroll
        for (int ks = 0; ks < 4; ks++) {
            uint32_t a0[4], a1[4];
            const int kca = 2 * ks + akc_half;
            ldsm_x4(sA[cur] + (uint32_t)(arow0 << 7) + (uint32_t)(((kca ^ (arow0 & 7)) << 4)),
                    a0[0], a0[1], a0[2], a0[3]);
            ldsm_x4(sA[cur] + (uint32_t)(arow1 << 7) + (uint32_t)(((kca ^ (arow1 & 7)) << 4)),
                    a1[0], a1[1], a1[2], a1[3]);
            const int kcb = 2 * ks + bkc_half;
            uint32_t b[4][4];
            #pragma unroll
            for (int p = 0; p < 4; p++) {
                const int brow = brow_base + p * 16;
                ldsm_x4(sB[cur] + (uint32_t)(brow << 7) + (uint32_t)(((kcb ^ (brow & 7)) << 4)),
                        b[p][0], b[p][1], b[p][2], b[p][3]);
            }
            #pragma unroll
            for (int p = 0; p < 4; p++) {
                mma_bf16(acc[0][2 * p + 0], a0, &b[p][0]);
                mma_bf16(acc[0][2 * p + 1], a0, &b[p][2]);
                mma_bf16(acc[1][2 * p + 0], a1, &b[p][0]);
                mma_bf16(acc[1][2 * p + 1], a1, &b[p][2]);
            }
        }
    }

    // Epilogue: relu(acc+bias) -> split bf16 [hi | lo] into g_hbf
    const int grpID = lane >> 2;
    const int tg    = lane & 3;
    #pragma unroll
    for (int mt = 0; mt < 2; mt++) {
        const int row0 = block_m + warp_m * 32 + mt * 16 + grpID;
        const int row1 = row0 + 8;
        #pragma unroll
        for (int nt = 0; nt < 8; nt++) {
            const int col = block_n + warp_n * 64 + nt * 8 + tg * 2;
            const float bi0 = bias[col], bi1 = bias[col + 1];
            {
                float v0 = fmaxf(acc[mt][nt][0] + bi0, 0.f);
                float v1 = fmaxf(acc[mt][nt][1] + bi1, 0.f);
                BfPair hp, lp;
                hp.h[0] = __float2bfloat16(v0);
                hp.h[1] = __float2bfloat16(v1);
                lp.h[0] = __float2bfloat16(v0 - __bfloat162float(hp.h[0]));
                lp.h[1] = __float2bfloat16(v1 - __bfloat162float(hp.h[1]));
                size_t base = (size_t)row0 * KA2;
                *(uint32_t*)&g_hbf[base + col]        = hp.u;
                *(uint32_t*)&g_hbf[base + 2048 + col] = lp.u;
            }
            {
                float v0 = fmaxf(acc[mt][nt][2] + bi0, 0.f);
                float v1 = fmaxf(acc[mt][nt][3] + bi1, 0.f);
                BfPair hp, lp;
                hp.h[0] = __float2bfloat16(v0);
                hp.h[1] = __float2bfloat16(v1);
                lp.h[0] = __float2bfloat16(v0 - __bfloat162float(hp.h[0]));
                lp.h[1] = __float2bfloat16(v1 - __bfloat162float(hp.h[1]));
                size_t base = (size_t)row1 * KA2;
                *(uint32_t*)&g_hbf[base + col]        = hp.u;
                *(uint32_t*)&g_hbf[base + 2048 + col] = lp.u;
            }
        }
    }
}

// ---------------------------------------------------------------------------
// GEMM2 (mma.sync bf16): g_t = h' @ W2'^T  (3-product split over 96 K-chunks)
// 64x48x64 tile, 128 threads, 4-stage cp.async pipeline (same safe ordering).
// ---------------------------------------------------------------------------
#define STAGE2_BYTES (BM2 * BK * 2 + BN2 * BK * 2)   // 14336
#define GEMM2_SMEM   (4 * STAGE2_BYTES)              // 57344

__global__ __launch_bounds__(128, 4)
void gemm2_mma_kernel() {
    extern __shared__ char dsm[];
    const uint32_t sbase = smem_u32(dsm);
    const int tid  = threadIdx.x;
    const int wid  = tid >> 5;
    const int lane = tid & 31;
    const int block_m = blockIdx.x * BM2;

    uint32_t sA[4], sB[4];
    #pragma unroll
    for (int s = 0; s < 4; s++) {
        sA[s] = sbase + s * STAGE2_BYTES;
        sB[s] = sA[s] + (uint32_t)(BM2 * BK * 2);
    }

    auto load_stage = [&](int kt, int s) {
        const int ka = ((kt < 32) ? kt : kt - 32) * BK;
        const int kb = ((kt < 64) ? kt : kt - 64) * BK;
        #pragma unroll
        for (int i = 0; i < 4; i++) {
            int t = tid + i * 128;
            int row = t >> 3, c = t & 7;
            uint32_t sw = (uint32_t)(row << 7) + (uint32_t)(((c ^ (row & 7)) << 4));
            cp_async16(sA[s] + sw, &g_hbf[(size_t)(block_m + row) * KA2 + ka + c * 8]);
        }
        #pragma unroll
        for (int i = 0; i < 3; i++) {
            int t = tid + i * 128;
            int row = t >> 3, c = t & 7;
            uint32_t sw = (uint32_t)(row << 7) + (uint32_t)(((c ^ (row & 7)) << 4));
            cp_async16(sB[s] + sw, &g_W2bf[(size_t)row * KA2 + kb + c * 8]);
        }
        cp_commit();
    };

    const int grp  = lane >> 3;
    const int lrow = lane & 7;
    const int arow = wid * 16 + ((grp & 1) << 3) + lrow;
    const int akc_half = grp >> 1;
    const int brow_base = ((grp >> 1) << 3) + lrow;
    const int bkc_half = grp & 1;

    float acc[6][4];
    #pragma unroll
    for (int j = 0; j < 6; j++)
        #pragma unroll
        for (int q = 0; q < 4; q++) acc[j][q] = 0.0f;

    load_stage(0, 0);
    load_stage(1, 1);
    load_stage(2, 2);

    for (int kt = 0; kt < NKIT2; kt++) {
        const int cur = kt & 3;
        if      (kt <= NKIT2 - 3) cp_wait<2>();
        else if (kt == NKIT2 - 2) cp_wait<1>();
        else                      cp_wait<0>();
        __syncthreads();
        if (kt + 3 < NKIT2) load_stage(kt + 3, (kt + 3) & 3);

        #pragma unroll
        for (int ks = 0; ks < 4; ks++) {
            uint32_t a[4];
            const int kca = 2 * ks + akc_half;
            ldsm_x4(sA[cur] + (uint32_t)(arow << 7) + (uint32_t)(((kca ^ (arow & 7)) << 4)),
                    a[0], a[1], a[2], a[3]);
            const int kcb = 2 * ks + bkc_half;
            uint32_t b[3][4];
            #pragma unroll
            for (int p = 0; p < 3; p++) {
                const int brow = brow_base + p * 16;
                ldsm_x4(sB[cur] + (uint32_t)(brow << 7) + (uint32_t)(((kcb ^ (brow & 7)) << 4)),
                        b[p][0], b[p][1], b[p][2], b[p][3]);
            }
            #pragma unroll
            for (int p = 0; p < 3; p++) {
                mma_bf16(acc[2 * p + 0], a, &b[p][0]);
                mma_bf16(acc[2 * p + 1], a, &b[p][2]);
            }
        }
    }

    // Epilogue: write 40 real columns
    const int grpID = lane >> 2;
    const int tg    = lane & 3;
    const int row0 = block_m + wid * 16 + grpID;
    const int row1 = row0 + 8;
    #pragma unroll
    for (int nt = 0; nt < 5; nt++) {
        const int col = nt * 8 + tg * 2;
        if (row0 < NNODES)
            *(float2*)&g_t[(size_t)row0 * NCLS + col] = make_float2(acc[nt][0], acc[nt][1]);
        if (row1 < NNODES)
            *(float2*)&g_t[(size_t)row1 * NCLS + col] = make_float2(acc[nt][2], acc[nt][3]);
    }
}

// ---------------------------------------------------------------------------
// Layer-2 propagate + bias
// ---------------------------------------------------------------------------
__global__ void gather2_kernel(const float* __restrict__ b2, float* __restrict__ out) {
    int gw = (blockIdx.x * blockDim.x + threadIdx.x) >> 5;
    int lane = threadIdx.x & 31;
    if (gw >= NNODES) return;
    int i = gw;
    float di = g_dinv[i];
    float self = di * di;
    int c1 = lane + 32;
    float acc0 = 0.f, acc1 = 0.f;
    int beg = g_rowptr[i], end = g_rowptr[i + 1];
    for (int j = beg; j < end; j++) {
        int s = g_csr_src[j];
        float c = g_csr_coef[j];
        acc0 += c * g_t[(size_t)s * NCLS + lane];
        if (lane < 8) acc1 += c * g_t[(size_t)s * NCLS + c1];
    }
    out[(size_t)i * NCLS + lane] = acc0 + self * g_t[(size_t)i * NCLS + lane] + b2[lane];
    if (lane < 8)
        out[(size_t)i * NCLS + c1] = acc1 + self * g_t[(size_t)i * NCLS + c1] + b2[c1];
}

// ---------------------------------------------------------------------------
// Entry point
// ---------------------------------------------------------------------------
extern "C" void kernel_launch(void* const* d_in, const int* in_sizes, int n_in,
                              void* d_out, int out_size) {
    const float* x   = (const float*)d_in[0];
    const int*   ei  = (const int*)d_in[1];
    const float* W1  = (const float*)d_in[2];
    const float* b1  = (const float*)d_in[3];
    const float* W2  = (const float*)d_in[4];
    const float* b2  = (const float*)d_in[5];
    float*       out = (float*)d_out;

    const int* src = ei;
    const int* dst = ei + NEDGES;

    cudaFuncSetAttribute(gemm1_mma_kernel,
                         cudaFuncAttributeMaxDynamicSharedMemorySize, GEMM1_SMEM);
    cudaFuncSetAttribute(gemm2_mma_kernel,
                         cudaFuncAttributeMaxDynamicSharedMemorySize, GEMM2_SMEM);

    // CSR build
    zero_cnt_kernel<<<40, 256>>>();
    count_kernel<<<(NEDGES + 255) / 256, 256>>>(dst);
    scan_kernel<<<1, 1024>>>();
    dinv_cursor_kernel<<<40, 256>>>();
    fill_kernel<<<(NEDGES + 255) / 256, 256>>>(src, dst);

    // Weight preps
    {
        dim3 grid(DIN / 32, DHID / 32), block(32, 8);
        w1prep_kernel<<<grid, block>>>(W1);
    }
    w2prep_kernel<<<BN2, 256>>>(W2);

    // Layer 1
    gather1_kernel<<<NNODES, 128>>>(x);
    {
        dim3 grid(DHID / BN, GA_ROWS / BM);   // (8, 79)
        gemm1_mma_kernel<<<grid, 512, GEMM1_SMEM>>>(b1);
    }

    // Layer 2
    gemm2_mma_kernel<<<GA_ROWS / BM2, 128, GEMM2_SMEM>>>();
    gather2_kernel<<<(NNODES * 32 + 127) / 128, 128>>>(b2, out);
}

// round 7
// speedup vs baseline: 1.1657x; 1.1657x over previous
#include <cuda_runtime.h>
#include <cuda_bf16.h>
#include <math.h>
#include <stdint.h>

// Problem constants (fixed by the reference)
#define NNODES 10000
#define NEDGES 320000
#define DIN    512
#define DHID   2048
#define NCLS   40

#define GA_ROWS 10112             // 79 * 128 (padded M; pad rows stay zero)

// GEMM1: A'[M x 1024]=[hi|lo], B'(W1^T)[2048 x 1536]=[hi|lo|hi], 24 K-chunks
#define KA1     1024
#define KB1     1536
#define BM      128
#define BN      128
#define BK      64                // 64 bf16 = 128 B per SMEM row
#define NKIT    24

// GEMM2: A2'(h')[M x 4096]=[hi|lo], B2'(W2^T)[48 x 4096]=[hi|lo]
// split-K by product term: z=0 hiA*hiB, z=1 hiA*loB, z=2 loA*hiB (32 chunks each)
#define KA2     4096
#define BM2     64
#define BN2     48                // padded from 40
#define NKIT2   32

// ---------------------------------------------------------------------------
// Device scratch (static globals: no runtime allocation allowed)
// ---------------------------------------------------------------------------
__device__ int   g_cnt[NNODES];
__device__ int   g_rowptr[NNODES + 1];
__device__ int   g_cursor[NNODES];
__device__ float g_dinv[NNODES];
__device__ int   g_csr_src[NEDGES];
__device__ float g_csr_coef[NEDGES];
__device__ __nv_bfloat16 g_Abf[(size_t)GA_ROWS * KA1];   // 20.7 MB
__device__ __nv_bfloat16 g_Bbf[(size_t)DHID * KB1];      // 6.3 MB
__device__ __nv_bfloat16 g_hbf[(size_t)GA_ROWS * KA2];   // 82.8 MB
__device__ __nv_bfloat16 g_W2bf[(size_t)BN2 * KA2];      // 393 KB
__device__ float g_t3[3][(size_t)NNODES * NCLS];         // 4.8 MB
__device__ float g_t[(size_t)NNODES * NCLS];             // 1.6 MB

// ---------------------------------------------------------------------------
// PTX helpers (baseline sm_80+ ISA: cp.async / ldmatrix / mma.sync)
// ---------------------------------------------------------------------------
__device__ __forceinline__ uint32_t smem_u32(const void* p) {
    uint32_t a;
    asm("{ .reg .u64 t; cvta.to.shared.u64 t, %1; cvt.u32.u64 %0, t; }"
        : "=r"(a) : "l"(p));
    return a;
}
__device__ __forceinline__ void cp_async16(uint32_t saddr, const void* gaddr) {
    asm volatile("cp.async.cg.shared.global [%0], [%1], 16;"
                 :: "r"(saddr), "l"(gaddr) : "memory");
}
__device__ __forceinline__ void cp_commit() {
    asm volatile("cp.async.commit_group;" ::: "memory");
}
template <int N>
__device__ __forceinline__ void cp_wait() {
    asm volatile("cp.async.wait_group %0;" :: "n"(N) : "memory");
}
__device__ __forceinline__ void ldsm_x4(uint32_t addr, uint32_t& r0, uint32_t& r1,
                                        uint32_t& r2, uint32_t& r3) {
    asm volatile("ldmatrix.sync.aligned.m8n8.x4.shared.b16 {%0,%1,%2,%3}, [%4];"
                 : "=r"(r0), "=r"(r1), "=r"(r2), "=r"(r3) : "r"(addr));
}
__device__ __forceinline__ void mma_bf16(float* d, const uint32_t* a, const uint32_t* b) {
    asm volatile(
        "mma.sync.aligned.m16n8k16.row.col.f32.bf16.bf16.f32 "
        "{%0,%1,%2,%3}, {%4,%5,%6,%7}, {%8,%9}, {%0,%1,%2,%3};"
        : "+f"(d[0]), "+f"(d[1]), "+f"(d[2]), "+f"(d[3])
        : "r"(a[0]), "r"(a[1]), "r"(a[2]), "r"(a[3]), "r"(b[0]), "r"(b[1]));
}

union BfPair { __nv_bfloat16 h[2]; uint32_t u; };

// ---------------------------------------------------------------------------
// CSR construction
// ---------------------------------------------------------------------------
__global__ void zero_cnt_kernel() {
    for (int i = blockIdx.x * blockDim.x + threadIdx.x; i < NNODES;
         i += gridDim.x * blockDim.x)
        g_cnt[i] = 0;
}
__global__ void count_kernel(const int* __restrict__ dst) {
    int e = blockIdx.x * blockDim.x + threadIdx.x;
    if (e < NEDGES) atomicAdd(&g_cnt[dst[e]], 1);
}
__global__ void scan_kernel() {
    __shared__ int sh[1024];
    __shared__ int carry;
    int tid = threadIdx.x;
    if (tid == 0) { carry = 0; g_rowptr[0] = 0; }
    __syncthreads();
    for (int base = 0; base < NNODES; base += 1024) {
        int i = base + tid;
        int v = (i < NNODES) ? g_cnt[i] : 0;
        sh[tid] = v;
        __syncthreads();
        #pragma unroll
        for (int off = 1; off < 1024; off <<= 1) {
            int t = (tid >= off) ? sh[tid - off] : 0;
            __syncthreads();
            sh[tid] += t;
            __syncthreads();
        }
        int incl = sh[tid];
        if (i < NNODES) g_rowptr[i + 1] = carry + incl;
        __syncthreads();
        if (tid == 1023) carry += sh[1023];
        __syncthreads();
    }
}
__global__ void dinv_cursor_kernel() {
    for (int i = blockIdx.x * blockDim.x + threadIdx.x; i < NNODES;
         i += gridDim.x * blockDim.x) {
        g_dinv[i]   = rsqrtf((float)g_cnt[i] + 1.0f);
        g_cursor[i] = g_rowptr[i];
    }
}
__global__ void fill_kernel(const int* __restrict__ src, const int* __restrict__ dst) {
    int e = blockIdx.x * blockDim.x + threadIdx.x;
    if (e >= NEDGES) return;
    int s = src[e], d = dst[e];
    int p = atomicAdd(&g_cursor[d], 1);
    g_csr_src[p]  = s;
    g_csr_coef[p] = g_dinv[s] * g_dinv[d];
}

// ---------------------------------------------------------------------------
// W1 prep (tiled transpose): g_Bbf[n] = [hi(512) | lo(512) | hi(512)]
// ---------------------------------------------------------------------------
__global__ void w1prep_kernel(const float* __restrict__ W1) {
    __shared__ float tile[32][33];
    int k0 = blockIdx.x * 32, n0 = blockIdx.y * 32;
    int tx = threadIdx.x, ty = threadIdx.y;
    #pragma unroll
    for (int j = 0; j < 4; j++)
        tile[ty + 8 * j][tx] = W1[(size_t)(k0 + ty + 8 * j) * DHID + n0 + tx];
    __syncthreads();
    #pragma unroll
    for (int j = 0; j < 4; j++) {
        int n = n0 + ty + 8 * j;
        int k = k0 + tx;
        float w = tile[tx][ty + 8 * j];
        __nv_bfloat16 hi = __float2bfloat16(w);
        __nv_bfloat16 lo = __float2bfloat16(w - __bfloat162float(hi));
        __nv_bfloat16* row = &g_Bbf[(size_t)n * KB1];
        row[k]        = hi;
        row[512 + k]  = lo;
        row[1024 + k] = hi;
    }
}

// ---------------------------------------------------------------------------
// W2 prep: g_W2bf[n] = [hi(2048) | lo(2048)], rows 40..47 zero
// ---------------------------------------------------------------------------
__global__ void w2prep_kernel(const float* __restrict__ W2) {
    int n = blockIdx.x;                 // 0..47
    __nv_bfloat16* row = &g_W2bf[(size_t)n * KA2];
    for (int k = threadIdx.x; k < DHID; k += blockDim.x) {
        float w = (n < NCLS) ? W2[(size_t)k * NCLS + n] : 0.0f;
        __nv_bfloat16 hi = __float2bfloat16(w);
        __nv_bfloat16 lo = __float2bfloat16(w - __bfloat162float(hi));
        row[k]        = hi;
        row[2048 + k] = lo;
    }
}

// ---------------------------------------------------------------------------
// Layer-1 propagate + split pack: A'[i] = [hi | lo]
// ---------------------------------------------------------------------------
__global__ void gather1_kernel(const float* __restrict__ x) {
    int i = blockIdx.x;
    int f4 = threadIdx.x;
    float di = g_dinv[i];
    float self = di * di;
    float4 xv = ((const float4*)&x[(size_t)i * DIN])[f4];
    float4 acc;
    acc.x = self * xv.x; acc.y = self * xv.y;
    acc.z = self * xv.z; acc.w = self * xv.w;
    int beg = g_rowptr[i], end = g_rowptr[i + 1];
    for (int j = beg; j < end; j++) {
        int s = g_csr_src[j];
        float c = g_csr_coef[j];
        float4 v = ((const float4*)&x[(size_t)s * DIN])[f4];
        acc.x += c * v.x; acc.y += c * v.y;
        acc.z += c * v.z; acc.w += c * v.w;
    }
    float a[4] = {acc.x, acc.y, acc.z, acc.w};
    union { __nv_bfloat16 h[4]; uint2 u; } hp, lp;
    #pragma unroll
    for (int t = 0; t < 4; t++) {
        hp.h[t] = __float2bfloat16(a[t]);
        lp.h[t] = __float2bfloat16(a[t] - __bfloat162float(hp.h[t]));
    }
    int k = f4 * 4;
    __nv_bfloat16* row = &g_Abf[(size_t)i * KA1];
    *(uint2*)&row[k]       = hp.u;
    *(uint2*)&row[512 + k] = lp.u;
}

// ---------------------------------------------------------------------------
// GEMM1 (mma.sync bf16): h' = relu(A' @ B'^T + b1) stored split-bf16 [hi|lo]
// 128x128x64 tile, 256 threads (8 warps, 4x2, warp tile 32x64), 3-stage
// cp.async pipeline, occupancy 2 CTAs/SM. Proven double-barrier ordering:
//   compute(kt) -> sync -> load(kt+3) -> wait -> sync
// ---------------------------------------------------------------------------
#define STAGE_BYTES (BM * BK * 2 + BN * BK * 2)   // 32768
#define GEMM1_SMEM  (3 * STAGE_BYTES)             // 98304

__global__ __launch_bounds__(256, 2)
void gemm1_mma_kernel(const float* __restrict__ bias) {
    extern __shared__ char dsm[];
    const uint32_t sbase = smem_u32(dsm);
    const int tid  = threadIdx.x;
    const int wid  = tid >> 5;
    const int lane = tid & 31;
    const int warp_m = wid & 3;       // 4 warps over M=128
    const int warp_n = wid >> 2;      // 2 warps over N=128 (64 each)
    const int block_n = blockIdx.x * BN;
    const int block_m = blockIdx.y * BM;

    uint32_t sA[3], sB[3];
    #pragma unroll
    for (int s = 0; s < 3; s++) {
        sA[s] = sbase + s * STAGE_BYTES;
        sB[s] = sA[s] + (uint32_t)(BM * BK * 2);
    }

    auto load_stage = [&](int kt, int s) {
        const int ka = ((kt < 8) ? kt : kt - 8) * BK;
        const int kb = kt * BK;
        #pragma unroll
        for (int i = 0; i < 4; i++) {                 // A: 1024 chunks
            int t = tid + i * 256;
            int row = t >> 3, c = t & 7;
            uint32_t sw = (uint32_t)(row << 7) + (uint32_t)(((c ^ (row & 7)) << 4));
            cp_async16(sA[s] + sw, &g_Abf[(size_t)(block_m + row) * KA1 + ka + c * 8]);
        }
        #pragma unroll
        for (int i = 0; i < 4; i++) {                 // B: 1024 chunks
            int t = tid + i * 256;
            int row = t >> 3, c = t & 7;
            uint32_t sw = (uint32_t)(row << 7) + (uint32_t)(((c ^ (row & 7)) << 4));
            cp_async16(sB[s] + sw, &g_Bbf[(size_t)(block_n + row) * KB1 + kb + c * 8]);
        }
        cp_commit();
    };

    const int grp  = lane >> 3;
    const int lrow = lane & 7;
    const int arow0 = warp_m * 32 + ((grp & 1) << 3) + lrow;
    const int arow1 = arow0 + 16;
    const int akc_half = grp >> 1;
    const int brow_base = warp_n * 64 + ((grp >> 1) << 3) + lrow;
    const int bkc_half = grp & 1;

    float acc[2][8][4];
    #pragma unroll
    for (int i = 0; i < 2; i++)
        #pragma unroll
        for (int j = 0; j < 8; j++)
            #pragma unroll
            for (int q = 0; q < 4; q++) acc[i][j][q] = 0.0f;

    load_stage(0, 0);
    load_stage(1, 1);
    load_stage(2, 2);
    cp_wait<2>();          // stage 0 ready
    __syncthreads();

    for (int kt = 0; kt < NKIT; kt++) {
        const int cur = kt % 3;
        #pragma unroll
        for (int ks = 0; ks < 4; ks++) {
            uint32_t a0[4], a1[4];
            const int kca = 2 * ks + akc_half;
            ldsm_x4(sA[cur] + (uint32_t)(arow0 << 7) + (uint32_t)(((kca ^ (arow0 & 7)) << 4)),
                    a0[0], a0[1], a0[2], a0[3]);
            ldsm_x4(sA[cur] + (uint32_t)(arow1 << 7) + (uint32_t)(((kca ^ (arow1 & 7)) << 4)),
                    a1[0], a1[1], a1[2], a1[3]);
            const int kcb = 2 * ks + bkc_half;
            uint32_t b[4][4];
            #pragma unroll
            for (int p = 0; p < 4; p++) {
                const int brow = brow_base + p * 16;
                ldsm_x4(sB[cur] + (uint32_t)(brow << 7) + (uint32_t)(((kcb ^ (brow & 7)) << 4)),
                        b[p][0], b[p][1], b[p][2], b[p][3]);
            }
            #pragma unroll
            for (int p = 0; p < 4; p++) {
                mma_bf16(acc[0][2 * p + 0], a0, &b[p][0]);
                mma_bf16(acc[0][2 * p + 1], a0, &b[p][2]);
                mma_bf16(acc[1][2 * p + 0], a1, &b[p][0]);
                mma_bf16(acc[1][2 * p + 1], a1, &b[p][2]);
            }
        }
        if (kt == NKIT - 1) break;
        __syncthreads();                       // all warps done reading stage cur
        if (kt + 3 < NKIT) {
            load_stage(kt + 3, cur);           // reuse just-computed buffer
            cp_wait<2>();                      // stage kt+1 complete
        } else if (kt + 2 < NKIT) {
            cp_wait<1>();
        } else {
            cp_wait<0>();
        }
        __syncthreads();                       // publish stage kt+1
    }

    // Epilogue: relu(acc+bias) -> split bf16 [hi | lo] into g_hbf
    const int grpID = lane >> 2;
    const int tg    = lane & 3;
    #pragma unroll
    for (int mt = 0; mt < 2; mt++) {
        const int row0 = block_m + warp_m * 32 + mt * 16 + grpID;
        const int row1 = row0 + 8;
        #pragma unroll
        for (int nt = 0; nt < 8; nt++) {
            const int col = block_n + warp_n * 64 + nt * 8 + tg * 2;
            const float bi0 = bias[col], bi1 = bias[col + 1];
            {
                float v0 = fmaxf(acc[mt][nt][0] + bi0, 0.f);
                float v1 = fmaxf(acc[mt][nt][1] + bi1, 0.f);
                BfPair hp, lp;
                hp.h[0] = __float2bfloat16(v0);
                hp.h[1] = __float2bfloat16(v1);
                lp.h[0] = __float2bfloat16(v0 - __bfloat162float(hp.h[0]));
                lp.h[1] = __float2bfloat16(v1 - __bfloat162float(hp.h[1]));
                size_t base = (size_t)row0 * KA2;
                *(uint32_t*)&g_hbf[base + col]        = hp.u;
                *(uint32_t*)&g_hbf[base + 2048 + col] = lp.u;
            }
            {
                float v0 = fmaxf(acc[mt][nt][2] + bi0, 0.f);
                float v1 = fmaxf(acc[mt][nt][3] + bi1, 0.f);
                BfPair hp, lp;
                hp.h[0] = __float2bfloat16(v0);
                hp.h[1] = __float2bfloat16(v1);
                lp.h[0] = __float2bfloat16(v0 - __bfloat162float(hp.h[0]));
                lp.h[1] = __float2bfloat16(v1 - __bfloat162float(hp.h[1]));
                size_t base = (size_t)row1 * KA2;
                *(uint32_t*)&g_hbf[base + col]        = hp.u;
                *(uint32_t*)&g_hbf[base + 2048 + col] = lp.u;
            }
        }
    }
}

// ---------------------------------------------------------------------------
// GEMM2 (mma.sync bf16, split-K by term): g_t3[z] = termz(h' @ W2'^T)
// z=0: hiA*hiB, z=1: hiA*loB, z=2: loA*hiB. 64x48x64 tile, 128 threads,
// 3-stage pipeline, 32 chunks per CTA. Deterministic (separate buffers).
// ---------------------------------------------------------------------------
#define STAGE2_BYTES (BM2 * BK * 2 + BN2 * BK * 2)   // 14336
#define GEMM2_SMEM   (3 * STAGE2_BYTES)              // 43008

__global__ __launch_bounds__(128, 4)
void gemm2_mma_kernel() {
    extern __shared__ char dsm[];
    const uint32_t sbase = smem_u32(dsm);
    const int tid  = threadIdx.x;
    const int wid  = tid >> 5;
    const int lane = tid & 31;
    const int block_m = blockIdx.x * BM2;
    const int z = blockIdx.y;                 // product term
    const int kaBase = (z == 2) ? 32 : 0;     // A: lo half for z=2
    const int kbBase = (z == 1) ? 32 : 0;     // B: lo half for z=1

    uint32_t sA[3], sB[3];
    #pragma unroll
    for (int s = 0; s < 3; s++) {
        sA[s] = sbase + s * STAGE2_BYTES;
        sB[s] = sA[s] + (uint32_t)(BM2 * BK * 2);
    }

    auto load_stage = [&](int kt, int s) {
        const int ka = (kaBase + kt) * BK;
        const int kb = (kbBase + kt) * BK;
        #pragma unroll
        for (int i = 0; i < 4; i++) {
            int t = tid + i * 128;
            int row = t >> 3, c = t & 7;
            uint32_t sw = (uint32_t)(row << 7) + (uint32_t)(((c ^ (row & 7)) << 4));
            cp_async16(sA[s] + sw, &g_hbf[(size_t)(block_m + row) * KA2 + ka + c * 8]);
        }
        #pragma unroll
        for (int i = 0; i < 3; i++) {
            int t = tid + i * 128;
            int row = t >> 3, c = t & 7;
            uint32_t sw = (uint32_t)(row << 7) + (uint32_t)(((c ^ (row & 7)) << 4));
            cp_async16(sB[s] + sw, &g_W2bf[(size_t)row * KA2 + kb + c * 8]);
        }
        cp_commit();
    };

    const int grp  = lane >> 3;
    const int lrow = lane & 7;
    const int arow = wid * 16 + ((grp & 1) << 3) + lrow;
    const int akc_half = grp >> 1;
    const int brow_base = ((grp >> 1) << 3) + lrow;
    const int bkc_half = grp & 1;

    float acc[6][4];
    #pragma unroll
    for (int j = 0; j < 6; j++)
        #pragma unroll
        for (int q = 0; q < 4; q++) acc[j][q] = 0.0f;

    load_stage(0, 0);
    load_stage(1, 1);
    load_stage(2, 2);
    cp_wait<2>();
    __syncthreads();

    for (int kt = 0; kt < NKIT2; kt++) {
        const int cur = kt % 3;
        #pragma unroll
        for (int ks = 0; ks < 4; ks++) {
            uint32_t a[4];
            const int kca = 2 * ks + akc_half;
            ldsm_x4(sA[cur] + (uint32_t)(arow << 7) + (uint32_t)(((kca ^ (arow & 7)) << 4)),
                    a[0], a[1], a[2], a[3]);
            const int kcb = 2 * ks + bkc_half;
            uint32_t b[3][4];
            #pragma unroll
            for (int p = 0; p < 3; p++) {
                const int brow = brow_base + p * 16;
                ldsm_x4(sB[cur] + (uint32_t)(brow << 7) + (uint32_t)(((kcb ^ (brow & 7)) << 4)),
                        b[p][0], b[p][1], b[p][2], b[p][3]);
            }
            #pragma unroll
            for (int p = 0; p < 3; p++) {
                mma_bf16(acc[2 * p + 0], a, &b[p][0]);
                mma_bf16(acc[2 * p + 1], a, &b[p][2]);
            }
        }
        if (kt == NKIT2 - 1) break;
        __syncthreads();
        if (kt + 3 < NKIT2) {
            load_stage(kt + 3, cur);
            cp_wait<2>();
        } else if (kt + 2 < NKIT2) {
            cp_wait<1>();
        } else {
            cp_wait<0>();
        }
        __syncthreads();
    }

    // Epilogue: write 40 real columns to this term's buffer
    float* dst = g_t3[z];
    const int grpID = lane >> 2;
    const int tg    = lane & 3;
    const int row0 = block_m + wid * 16 + grpID;
    const int row1 = row0 + 8;
    #pragma unroll
    for (int nt = 0; nt < 5; nt++) {
        const int col = nt * 8 + tg * 2;
        if (row0 < NNODES)
            *(float2*)&dst[(size_t)row0 * NCLS + col] = make_float2(acc[nt][0], acc[nt][1]);
        if (row1 < NNODES)
            *(float2*)&dst[(size_t)row1 * NCLS + col] = make_float2(acc[nt][2], acc[nt][3]);
    }
}

// combine the 3 split-K terms: g_t = t0 + t1 + t2
__global__ void combine_kernel() {
    int i = blockIdx.x * blockDim.x + threadIdx.x;
    const int total = NNODES * NCLS / 4;
    if (i >= total) return;
    float4 a = ((const float4*)g_t3[0])[i];
    float4 b = ((const float4*)g_t3[1])[i];
    float4 c = ((const float4*)g_t3[2])[i];
    float4 r;
    r.x = a.x + b.x + c.x;
    r.y = a.y + b.y + c.y;
    r.z = a.z + b.z + c.z;
    r.w = a.w + b.w + c.w;
    ((float4*)g_t)[i] = r;
}

// ---------------------------------------------------------------------------
// Layer-2 propagate + bias
// ---------------------------------------------------------------------------
__global__ void gather2_kernel(const float* __restrict__ b2, float* __restrict__ out) {
    int gw = (blockIdx.x * blockDim.x + threadIdx.x) >> 5;
    int lane = threadIdx.x & 31;
    if (gw >= NNODES) return;
    int i = gw;
    float di = g_dinv[i];
    float self = di * di;
    int c1 = lane + 32;
    float acc0 = 0.f, acc1 = 0.f;
    int beg = g_rowptr[i], end = g_rowptr[i + 1];
    for (int j = beg; j < end; j++) {
        int s = g_csr_src[j];
        float c = g_csr_coef[j];
        acc0 += c * g_t[(size_t)s * NCLS + lane];
        if (lane < 8) acc1 += c * g_t[(size_t)s * NCLS + c1];
    }
    out[(size_t)i * NCLS + lane] = acc0 + self * g_t[(size_t)i * NCLS + lane] + b2[lane];
    if (lane < 8)
        out[(size_t)i * NCLS + c1] = acc1 + self * g_t[(size_t)i * NCLS + c1] + b2[c1];
}

// ---------------------------------------------------------------------------
// Entry point
// ---------------------------------------------------------------------------
extern "C" void kernel_launch(void* const* d_in, const int* in_sizes, int n_in,
                              void* d_out, int out_size) {
    const float* x   = (const float*)d_in[0];
    const int*   ei  = (const int*)d_in[1];
    const float* W1  = (const float*)d_in[2];
    const float* b1  = (const float*)d_in[3];
    const float* W2  = (const float*)d_in[4];
    const float* b2  = (const float*)d_in[5];
    float*       out = (float*)d_out;

    const int* src = ei;
    const int* dst = ei + NEDGES;

    cudaFuncSetAttribute(gemm1_mma_kernel,
                         cudaFuncAttributeMaxDynamicSharedMemorySize, GEMM1_SMEM);
    cudaFuncSetAttribute(gemm2_mma_kernel,
                         cudaFuncAttributeMaxDynamicSharedMemorySize, GEMM2_SMEM);

    // CSR build
    zero_cnt_kernel<<<40, 256>>>();
    count_kernel<<<(NEDGES + 255) / 256, 256>>>(dst);
    scan_kernel<<<1, 1024>>>();
    dinv_cursor_kernel<<<40, 256>>>();
    fill_kernel<<<(NEDGES + 255) / 256, 256>>>(src, dst);

    // Weight preps
    {
        dim3 grid(DIN / 32, DHID / 32), block(32, 8);
        w1prep_kernel<<<grid, block>>>(W1);
    }
    w2prep_kernel<<<BN2, 256>>>(W2);

    // Layer 1
    gather1_kernel<<<NNODES, 128>>>(x);
    {
        dim3 grid(DHID / BN, GA_ROWS / BM);   // (16, 79)
        gemm1_mma_kernel<<<grid, 256, GEMM1_SMEM>>>(b1);
    }

    // Layer 2 (split-K gemm + combine + propagate)
    {
        dim3 grid(GA_ROWS / BM2, 3);          // (158, 3)
        gemm2_mma_kernel<<<grid, 128, GEMM2_SMEM>>>();
    }
    combine_kernel<<<(NNODES * NCLS / 4 + 255) / 256, 256>>>();
    gather2_kernel<<<(NNODES * 32 + 127) / 128, 128>>>(b2, out);
}